// round 7
// baseline (speedup 1.0000x reference)
#include <cuda_runtime.h>
#include <cstddef>

typedef unsigned long long u64;

// ---- scalar/bias parameters in constant (low traffic) ----
__constant__ float cB0[64], cB1[64];
__constant__ float cF1b[16], cF2b[16];
__constant__ float cDB[64];
__constant__ float cEps[4];

// ---- packed f32x2 primitives ----
__device__ __forceinline__ u64 pk(float lo, float hi) {
    u64 r; asm("mov.b64 %0,{%1,%2};" : "=l"(r) : "f"(lo), "f"(hi)); return r;
}
__device__ __forceinline__ void upk(u64 p, float& a, float& b) {
    asm("mov.b64 {%0,%1},%2;" : "=f"(a), "=f"(b) : "l"(p));
}
__device__ __forceinline__ u64 fma2(u64 a, u64 b, u64 c) {
    u64 d; asm("fma.rn.f32x2 %0,%1,%2,%3;" : "=l"(d) : "l"(a), "l"(b), "l"(c)); return d;
}
__device__ __forceinline__ u64 mul2(u64 a, u64 b) {
    u64 d; asm("mul.rn.f32x2 %0,%1,%2;" : "=l"(d) : "l"(a), "l"(b)); return d;
}
__device__ __forceinline__ u64 add2(u64 a, u64 b) {
    u64 d; asm("add.rn.f32x2 %0,%1,%2;" : "=l"(d) : "l"(a), "l"(b)); return d;
}

// dot: 16-float smem row (16B aligned, LDS.128) with packed 8xf32x2 vector
__device__ __forceinline__ float dot16s(const float* __restrict__ w, const u64* v) {
    const ulonglong2* w2 = (const ulonglong2*)w;
    ulonglong2 p0 = w2[0], p1 = w2[1], p2 = w2[2], p3 = w2[3];
    u64 a0 = mul2(p0.x, v[0]);
    u64 a1 = mul2(p0.y, v[1]);
    a0 = fma2(p1.x, v[2], a0);
    a1 = fma2(p1.y, v[3], a1);
    a0 = fma2(p2.x, v[4], a0);
    a1 = fma2(p2.y, v[5], a1);
    a0 = fma2(p3.x, v[6], a0);
    a1 = fma2(p3.y, v[7], a1);
    a0 = add2(a0, a1);
    float x, y; upk(a0, x, y);
    return x + y;
}

__global__ __launch_bounds__(128, 5) void gvae_kernel(
    const float* __restrict__ adj,       // [B,4,13,13]
    const float* __restrict__ init_w,    // [13,16]
    const float* __restrict__ w0g, const float* __restrict__ w1g,
    const float* __restrict__ dwg,       // [4,16,16] each
    const float* __restrict__ fc1w, const float* __restrict__ fc2w, // [16,16]
    const float* __restrict__ big, const float* __restrict__ bib,
    const float* __restrict__ bim, const float* __restrict__ biv,
    const float* __restrict__ bog, const float* __restrict__ bob,
    const float* __restrict__ bom, const float* __restrict__ bov,
    float* __restrict__ out, int B)
{
    __shared__ __align__(16) float sW0[1024], sW1[1024], sDW[1024];  // 12 KB
    __shared__ __align__(16) float sWi[208];                         // init_weight
    __shared__ __align__(16) float sF1[256], sF2[256];               // fc1/fc2
    __shared__ float sSin[52], sTin[52], sSout[52], sTout[52];       // folded BN
    __shared__ __align__(16) float scr[4 * 1352];                    // raw adj / adjT
    __shared__ __align__(16) float xbs[4 * 416];                     // x broadcast

    const int tid = threadIdx.x;
    for (int t = tid; t < 1024; t += 128) { sW0[t] = w0g[t]; sW1[t] = w1g[t]; sDW[t] = dwg[t]; }
    for (int t = tid; t < 208;  t += 128) sWi[t] = init_w[t];
    for (int t = tid; t < 256;  t += 128) { sF1[t] = fc1w[t]; sF2[t] = fc2w[t]; }
    for (int t = tid; t < 52; t += 128) {
        float si = big[t] * rsqrtf(biv[t] + 1e-5f);
        sSin[t]  = si; sTin[t]  = bib[t] - bim[t] * si;
        float so = bog[t] * rsqrtf(bov[t] + 1e-5f);
        sSout[t] = so; sTout[t] = bob[t] - bom[t] * so;
    }
    __syncthreads();

    const int w    = tid >> 5;
    const int lane = tid & 31;
    const int sub  = lane >> 4;            // 2 graphs per warp
    const int n    = lane & 15;            // node id; active if n < 13
    const int nn   = (n < 13) ? n : 12;
    const long b0  = (long)blockIdx.x * 8 + (long)w * 2;
    if (b0 >= B) return;

    const size_t muOff = (size_t)B * 676;
    const size_t lvOff = muOff + (size_t)B * 208;
    float* scw = scr + w * 1352;           // raw adj -> adjT
    float* xb  = xbs + w * 416;            // [2][13][16] broadcast

    // ---- stage raw adj coalesced ----
    {
        const float4* g  = (const float4*)(adj + (size_t)b0 * 676);
        float4*       s4 = (float4*)scw;
        for (int t = lane; t < 338; t += 32) s4[t] = g[t];
    }
    __syncwarp();

    // ---- read this lane's rows (transient regs), compute xp, write adjT ----
    float raw[4][13];
#pragma unroll
    for (int c = 0; c < 4; c++)
#pragma unroll
        for (int m = 0; m < 13; m++)
            raw[c][m] = scw[sub * 676 + c * 169 + nn * 13 + m];

    u64 xp[8];
    {
        float a0 = raw[0][0] + raw[1][0] + raw[2][0] + raw[3][0];
        u64 aa = pk(a0, a0);
        const ulonglong2* wm = (const ulonglong2*)sWi;
        ulonglong2 q0 = wm[0], q1 = wm[1], q2 = wm[2], q3 = wm[3];
        xp[0] = mul2(aa, q0.x); xp[1] = mul2(aa, q0.y);
        xp[2] = mul2(aa, q1.x); xp[3] = mul2(aa, q1.y);
        xp[4] = mul2(aa, q2.x); xp[5] = mul2(aa, q2.y);
        xp[6] = mul2(aa, q3.x); xp[7] = mul2(aa, q3.y);
#pragma unroll
        for (int m = 1; m < 13; m++) {
            float a = raw[0][m] + raw[1][m] + raw[2][m] + raw[3][m];
            u64 am = pk(a, a);
            const ulonglong2* wv = (const ulonglong2*)(sWi + m * 16);
            ulonglong2 p0 = wv[0], p1 = wv[1], p2 = wv[2], p3 = wv[3];
            xp[0] = fma2(am, p0.x, xp[0]); xp[1] = fma2(am, p0.y, xp[1]);
            xp[2] = fma2(am, p1.x, xp[2]); xp[3] = fma2(am, p1.y, xp[3]);
            xp[4] = fma2(am, p2.x, xp[4]); xp[5] = fma2(am, p2.y, xp[5]);
            xp[6] = fma2(am, p3.x, xp[6]); xp[7] = fma2(am, p3.y, xp[7]);
        }
    }
    __syncwarp();          // all raw reads done before adjT overwrites
    if (n < 13) {
        float4* adjT = (float4*)scw;
#pragma unroll
        for (int m = 0; m < 13; m++) {
            float4 v; v.x = raw[0][m]; v.y = raw[1][m]; v.z = raw[2][m]; v.w = raw[3][m];
            adjT[(sub * 13 + nn) * 13 + m] = v;
        }
    }
    __syncwarp();

    // ---- 4 GIN layers ----
    const float4* adjT = (const float4*)scw;
    for (int l = 0; l < 4; l++) {
        if (n < 13) {
            ulonglong2* xv = (ulonglong2*)(xb + (sub * 13 + nn) * 16);
#pragma unroll
            for (int q = 0; q < 4; q++) {
                ulonglong2 v; v.x = xp[2*q]; v.y = xp[2*q+1];
                xv[q] = v;
            }
        }
        __syncwarp();

        const float ep = 1.0f + cEps[l];
        const u64 ep2 = pk(ep, ep);
        u64 agg[8];
#pragma unroll
        for (int q = 0; q < 8; q++) agg[q] = mul2(ep2, xp[q]);
#pragma unroll
        for (int m = 0; m < 13; m++) {
            float4 a4 = adjT[(sub * 13 + nn) * 13 + m];
            const ulonglong2* xv = (const ulonglong2*)(xb + (sub * 13 + m) * 16);
            ulonglong2 v0 = xv[0], v1 = xv[1], v2 = xv[2], v3 = xv[3];
            u64 a0 = pk(a4.x, a4.x);
            u64 a1 = pk(a4.y, a4.y);
            u64 a2 = pk(a4.z, a4.z);
            u64 a3 = pk(a4.w, a4.w);
            agg[0] = fma2(a0, v0.x, agg[0]); agg[1] = fma2(a0, v0.y, agg[1]);
            agg[2] = fma2(a1, v1.x, agg[2]); agg[3] = fma2(a1, v1.y, agg[3]);
            agg[4] = fma2(a2, v2.x, agg[4]); agg[5] = fma2(a2, v2.y, agg[5]);
            agg[6] = fma2(a3, v3.x, agg[6]); agg[7] = fma2(a3, v3.y, agg[7]);
        }
        __syncwarp();      // xb free for next writer

        const float sin_  = sSin[l*13 + nn],  tin_  = sTin[l*13 + nn];
        const float sout_ = sSout[l*13 + nn], tout_ = sTout[l*13 + nn];
        u64 hp[8];
#pragma unroll
        for (int q = 0; q < 8; q++) {
            float acc0 = cB0[l*16 + 2*q]     + dot16s(sW0 + l*256 + (2*q)*16,   agg);
            float acc1 = cB0[l*16 + 2*q + 1] + dot16s(sW0 + l*256 + (2*q+1)*16, agg);
            float v0 = fmaf(sin_, acc0, tin_);
            float v1 = fmaf(sin_, acc1, tin_);
            hp[q] = pk(fmaxf(v0, 0.01f * v0), fmaxf(v1, 0.01f * v1));
        }
#pragma unroll
        for (int q = 0; q < 8; q++) {
            float acc0 = cB1[l*16 + 2*q]     + dot16s(sW1 + l*256 + (2*q)*16,   hp);
            float acc1 = cB1[l*16 + 2*q + 1] + dot16s(sW1 + l*256 + (2*q+1)*16, hp);
            float v0 = fmaf(sout_, acc0, tout_);
            float v1 = fmaf(sout_, acc1, tout_);
            xp[q] = pk(fmaxf(v0, 0.01f * v0), fmaxf(v1, 0.01f * v1));
        }
    }

    // ---- fc1 -> mu (=z), fc2 -> logvar ----
    u64 zp[8];
#pragma unroll
    for (int q = 0; q < 8; q++) {
        float z0 = cF1b[2*q]     + dot16s(sF1 + (2*q)*16,   xp);
        float z1 = cF1b[2*q + 1] + dot16s(sF1 + (2*q+1)*16, xp);
        zp[q] = pk(z0, z1);
    }
    if (n < 13) {
        ulonglong2* o = (ulonglong2*)(out + muOff + ((size_t)(b0 + sub) * 13 + n) * 16);
#pragma unroll
        for (int q = 0; q < 4; q++) {
            ulonglong2 v; v.x = zp[2*q]; v.y = zp[2*q+1];
            o[q] = v;
        }
        ulonglong2* o2 = (ulonglong2*)(out + lvOff + ((size_t)(b0 + sub) * 13 + n) * 16);
#pragma unroll
        for (int q = 0; q < 4; q++) {
            ulonglong2 v;
            v.x = pk(cF2b[4*q]   + dot16s(sF2 + (4*q)*16,   xp),
                     cF2b[4*q+1] + dot16s(sF2 + (4*q+1)*16, xp));
            v.y = pk(cF2b[4*q+2] + dot16s(sF2 + (4*q+2)*16, xp),
                     cF2b[4*q+3] + dot16s(sF2 + (4*q+3)*16, xp));
            o2[q] = v;
        }
    }

    // ---- decoder: per channel k, recon = relu(T T^T), direct STG ----
    for (int k = 0; k < 4; k++) {
        u64 tp2[8];
#pragma unroll
        for (int q = 0; q < 8; q++) {
            float t0 = cDB[k*16 + 2*q]     + dot16s(sDW + k*256 + (2*q)*16,   zp);
            float t1 = cDB[k*16 + 2*q + 1] + dot16s(sDW + k*256 + (2*q+1)*16, zp);
            tp2[q] = pk(t0, t1);
        }

        __syncwarp();      // prior readers of xb done
        if (n < 13) {
            ulonglong2* tv = (ulonglong2*)(xb + (sub * 13 + nn) * 16);
#pragma unroll
            for (int q = 0; q < 4; q++) {
                ulonglong2 v; v.x = tp2[2*q]; v.y = tp2[2*q+1];
                tv[q] = v;
            }
        }
        __syncwarp();

        float* orow = out + ((size_t)(b0 + sub) * 4 + k) * 169 + nn * 13;
#pragma unroll
        for (int m = 0; m < 13; m++) {
            const ulonglong2* tv = (const ulonglong2*)(xb + (sub * 13 + m) * 16);
            ulonglong2 v0 = tv[0], v1 = tv[1], v2 = tv[2], v3 = tv[3];
            u64 s0 = mul2(tp2[0], v0.x);
            u64 s1 = mul2(tp2[1], v0.y);
            s0 = fma2(tp2[2], v1.x, s0);
            s1 = fma2(tp2[3], v1.y, s1);
            s0 = fma2(tp2[4], v2.x, s0);
            s1 = fma2(tp2[5], v2.y, s1);
            s0 = fma2(tp2[6], v3.x, s0);
            s1 = fma2(tp2[7], v3.y, s1);
            s0 = add2(s0, s1);
            float x0, x1; upk(s0, x0, x1);
            if (n < 13) orow[m] = fmaxf(x0 + x1, 0.0f);
        }
    }
}

extern "C" void kernel_launch(void* const* d_in, const int* in_sizes, int n_in,
                              void* d_out, int out_size) {
    cudaMemcpyToSymbolAsync(cEps, d_in[2],    4 * 4, 0, cudaMemcpyDeviceToDevice);
    cudaMemcpyToSymbolAsync(cB0,  d_in[4],   64 * 4, 0, cudaMemcpyDeviceToDevice);
    cudaMemcpyToSymbolAsync(cB1,  d_in[6],   64 * 4, 0, cudaMemcpyDeviceToDevice);
    cudaMemcpyToSymbolAsync(cF1b, d_in[16],  16 * 4, 0, cudaMemcpyDeviceToDevice);
    cudaMemcpyToSymbolAsync(cF2b, d_in[18],  16 * 4, 0, cudaMemcpyDeviceToDevice);
    cudaMemcpyToSymbolAsync(cDB,  d_in[20],  64 * 4, 0, cudaMemcpyDeviceToDevice);

    const float* adj = (const float*)d_in[0];
    float* out = (float*)d_out;
    int B = in_sizes[0] / 676;
    int grid = (B + 7) / 8;
    gvae_kernel<<<grid, 128>>>(adj,
        (const float*)d_in[1],
        (const float*)d_in[3],  (const float*)d_in[5],  (const float*)d_in[19],
        (const float*)d_in[15], (const float*)d_in[17],
        (const float*)d_in[7],  (const float*)d_in[8],
        (const float*)d_in[9],  (const float*)d_in[10],
        (const float*)d_in[11], (const float*)d_in[12],
        (const float*)d_in[13], (const float*)d_in[14],
        out, B);
}